// round 1
// baseline (speedup 1.0000x reference)
#include <cuda_runtime.h>

// LSTM: T=8192 steps, H=128, batch=1, input_size=1.
// Single persistent CTA, 512 threads = one thread per gate row.
// Weights: 64/row in registers (f32x2 pairs), 64/row in padded smem.
// h broadcast via smem; two __syncthreads per step.

#define HD 128
#define NROWS 512
#define NTHREADS 512
#define W2_STRIDE 68   // 64 + 4 pad -> conflict-free LDS.128 across lanes

__device__ __forceinline__ unsigned long long ffma2(unsigned long long a,
                                                    unsigned long long b,
                                                    unsigned long long c) {
    unsigned long long d;
    asm("fma.rn.f32x2 %0, %1, %2, %3;" : "=l"(d) : "l"(a), "l"(b), "l"(c));
    return d;
}

__device__ __forceinline__ unsigned long long pack2(float lo, float hi) {
    unsigned long long r;
    asm("mov.b64 %0, {%1, %2};" : "=l"(r) : "f"(lo), "f"(hi));
    return r;
}

__device__ __forceinline__ void unpack2(unsigned long long v, float& lo, float& hi) {
    asm("mov.b64 {%0, %1}, %2;" : "=f"(lo), "=f"(hi) : "l"(v));
}

__device__ __forceinline__ float sigm(float x) {
    x = fminf(fmaxf(x, -30.f), 30.f);
    return __fdividef(1.f, 1.f + __expf(-x));
}

__device__ __forceinline__ float tanh_(float x) {
    x = fminf(fmaxf(x, -15.f), 15.f);
    float e = __expf(-2.f * x);
    return __fdividef(1.f - e, 1.f + e);
}

extern "C" __global__ void __launch_bounds__(NTHREADS, 1)
lstm_persistent_kernel(const float* __restrict__ x,      // [T]
                       const float* __restrict__ W_ih,   // [512] (input_size=1)
                       const float* __restrict__ W_hh,   // [512*128] row-major
                       const float* __restrict__ b_ih,   // [512]
                       const float* __restrict__ b_hh,   // [512]
                       const float* __restrict__ W_lin,  // [128]
                       const float* __restrict__ b_lin,  // [1]
                       const float* __restrict__ h0,     // [128]
                       const float* __restrict__ c0,     // [128]
                       float* __restrict__ out,          // [1]
                       int T) {
    extern __shared__ float smem[];
    float* w2   = smem;                         // [512 * W2_STRIDE]
    float* hs   = w2 + NROWS * W2_STRIDE;       // [128]
    float* gbuf = hs + HD;                      // [512]

    const int r = threadIdx.x;

    // Stage second-half weights (j = 64..127) into padded smem.
    for (int i = r; i < NROWS * 64; i += NTHREADS) {
        int row = i >> 6;
        int jj  = i & 63;
        w2[row * W2_STRIDE + jj] = W_hh[row * HD + 64 + jj];
    }

    // Init h, c from h0/c0.
    if (r < HD) hs[r] = h0[r];
    float c = (r < HD) ? c0[r] : 0.f;

    // Per-row constants.
    const float wih  = W_ih[r];
    const float bsum = b_ih[r] + b_hh[r];

    // First-half weights (j = 0..63) in registers as 32 packed f32x2.
    unsigned long long wr[32];
    {
        const ulonglong2* wg = (const ulonglong2*)(W_hh + (size_t)r * HD);
        #pragma unroll
        for (int k = 0; k < 16; ++k) {
            ulonglong2 v = wg[k];
            wr[2 * k]     = v.x;
            wr[2 * k + 1] = v.y;
        }
    }
    __syncthreads();

    const ulonglong2* hs2 = (const ulonglong2*)hs;                     // 32 x 16B chunks
    const ulonglong2* w22 = (const ulonglong2*)(w2 + r * W2_STRIDE);   // 16 x 16B chunks

    for (int t = 0; t < T; ++t) {
        float xt = __ldg(&x[t]);  // broadcast, L1-resident
        unsigned long long acc0 = pack2(fmaf(wih, xt, bsum), 0.f);
        unsigned long long acc1 = pack2(0.f, 0.f);

        // j = 0..63 : register weights
        #pragma unroll
        for (int k = 0; k < 16; ++k) {
            ulonglong2 hp = hs2[k];
            acc0 = ffma2(wr[2 * k],     hp.x, acc0);
            acc1 = ffma2(wr[2 * k + 1], hp.y, acc1);
        }
        // j = 64..127 : smem weights
        #pragma unroll
        for (int k = 0; k < 16; ++k) {
            ulonglong2 hp = hs2[16 + k];
            ulonglong2 wp = w22[k];
            acc0 = ffma2(wp.x, hp.x, acc0);
            acc1 = ffma2(wp.y, hp.y, acc1);
        }

        float a0, a1, b0, b1;
        unpack2(acc0, a0, a1);
        unpack2(acc1, b0, b1);
        float gpre = (a0 + b0) + (a1 + b1);

        // Gate rows: i:[0,128) f:[128,256) g:[256,384) o:[384,512) — warp-uniform branch.
        float act = (r < 256 || r >= 384) ? sigm(gpre) : tanh_(gpre);
        gbuf[r] = act;
        __syncthreads();

        if (r < HD) {
            float iv = gbuf[r];
            float fv = gbuf[HD + r];
            float gv = gbuf[2 * HD + r];
            float ov = gbuf[3 * HD + r];
            c = fmaf(fv, c, iv * gv);
            hs[r] = ov * tanh_(c);
        }
        __syncthreads();
    }

    // Final projection: pred = W_lin . h_T + b_lin
    if (r < HD) gbuf[r] = hs[r] * W_lin[r];
    __syncthreads();
    if (r == 0) {
        float s = b_lin[0];
        #pragma unroll 8
        for (int k = 0; k < HD; ++k) s += gbuf[k];
        out[0] = s;
    }
}

extern "C" void kernel_launch(void* const* d_in, const int* in_sizes, int n_in,
                              void* d_out, int out_size) {
    const float* x     = (const float*)d_in[0];
    const float* W_ih  = (const float*)d_in[1];
    const float* W_hh  = (const float*)d_in[2];
    const float* b_ih  = (const float*)d_in[3];
    const float* b_hh  = (const float*)d_in[4];
    const float* W_lin = (const float*)d_in[5];
    const float* b_lin = (const float*)d_in[6];
    const float* h0    = (const float*)d_in[7];
    const float* c0    = (const float*)d_in[8];
    float* out = (float*)d_out;

    const int T = in_sizes[0];  // 8192

    const size_t smem_bytes =
        (size_t)(NROWS * W2_STRIDE + HD + NROWS) * sizeof(float);  // ~142 KB

    // Opt-in to >48KB dynamic smem (idempotent; not a memory allocation).
    cudaFuncSetAttribute(lstm_persistent_kernel,
                         cudaFuncAttributeMaxDynamicSharedMemorySize,
                         (int)smem_bytes);

    lstm_persistent_kernel<<<1, NTHREADS, smem_bytes>>>(
        x, W_ih, W_hh, b_ih, b_hh, W_lin, b_lin, h0, c0, out, T);
}

// round 2
// speedup vs baseline: 1.3050x; 1.3050x over previous
#include <cuda_runtime.h>
#include <cstdint>

// LSTM T=8192, H=128, batch=1. Cluster of 2 CTAs x 256 threads (2 SMs).
// All 512x128 W_hh weights live in registers (128 regs/thread).
// CTA q owns rows {gate*128 + q*64 + jl} for gate in 0..3, jl in 0..63,
// hence computes h[q*64 .. q*64+64) locally; 64 floats cross via DSMEM per step.

#define HD 128
#define TPC 256
#define HALF 64

typedef unsigned long long u64;

__device__ __forceinline__ u64 ffma2(u64 a, u64 b, u64 c) {
    u64 d;
    asm("fma.rn.f32x2 %0, %1, %2, %3;" : "=l"(d) : "l"(a), "l"(b), "l"(c));
    return d;
}
__device__ __forceinline__ u64 pack2(float lo, float hi) {
    u64 r;
    asm("mov.b64 %0, {%1, %2};" : "=l"(r) : "f"(lo), "f"(hi));
    return r;
}
__device__ __forceinline__ void unpack2(u64 v, float& lo, float& hi) {
    asm("mov.b64 {%0, %1}, %2;" : "=f"(lo), "=f"(hi) : "l"(v));
}
__device__ __forceinline__ float sigm(float x) {
    x = fminf(fmaxf(x, -30.f), 30.f);
    return __fdividef(1.f, 1.f + __expf(-x));
}
__device__ __forceinline__ float tanh_(float x) {
    x = fminf(fmaxf(x, -15.f), 15.f);
    float e = __expf(-2.f * x);
    return __fdividef(1.f - e, 1.f + e);
}

__device__ __forceinline__ uint32_t smem_u32(const void* p) {
    return (uint32_t)__cvta_generic_to_shared(p);
}
__device__ __forceinline__ uint32_t mapa_u32(uint32_t addr, uint32_t rank) {
    uint32_t r;
    asm("mapa.shared::cluster.u32 %0, %1, %2;" : "=r"(r) : "r"(addr), "r"(rank));
    return r;
}
__device__ __forceinline__ void st_remote_f32(uint32_t addr, float v) {
    asm volatile("st.shared::cluster.f32 [%0], %1;" :: "r"(addr), "f"(v) : "memory");
}
__device__ __forceinline__ void mbar_init(uint32_t a, uint32_t cnt) {
    asm volatile("mbarrier.init.shared.b64 [%0], %1;" :: "r"(a), "r"(cnt) : "memory");
}
__device__ __forceinline__ void mbar_arrive_cluster(uint32_t a) {
    asm volatile("mbarrier.arrive.release.cluster.shared::cluster.b64 _, [%0];"
                 :: "r"(a) : "memory");
}
__device__ __forceinline__ void mbar_wait_cluster(uint32_t a, uint32_t parity) {
    asm volatile(
        "{\n\t"
        ".reg .pred P;\n\t"
        "WL_%=:\n\t"
        "mbarrier.try_wait.parity.acquire.cluster.shared::cta.b64 P, [%0], %1;\n\t"
        "@P bra WD_%=;\n\t"
        "bra WL_%=;\n\t"
        "WD_%=:\n\t"
        "}" :: "r"(a), "r"(parity) : "memory");
}
__device__ __forceinline__ void fence_cluster() {
    asm volatile("fence.acq_rel.cluster;" ::: "memory");
}
__device__ __forceinline__ void cluster_sync() {
    asm volatile("barrier.cluster.arrive.aligned;" ::: "memory");
    asm volatile("barrier.cluster.wait.aligned;" ::: "memory");
}

extern "C" __global__ void __launch_bounds__(TPC, 1) __cluster_dims__(2, 1, 1)
lstm_cluster_kernel(const float* __restrict__ x,      // [T]
                    const float* __restrict__ W_ih,   // [512]
                    const float* __restrict__ W_hh,   // [512*128]
                    const float* __restrict__ b_ih,   // [512]
                    const float* __restrict__ b_hh,   // [512]
                    const float* __restrict__ W_lin,  // [128]
                    const float* __restrict__ b_lin,  // [1]
                    const float* __restrict__ h0,     // [128]
                    const float* __restrict__ c0,     // [128]
                    float* __restrict__ out,          // [1]
                    int T) {
    __shared__ __align__(16) float hs[2][HD];   // double-buffered h
    __shared__ float gact[4 * HALF];            // this CTA's 256 activations
    __shared__ float red[8];
    __shared__ __align__(8) u64 mbar;

    const int r = threadIdx.x;
    uint32_t rank;
    asm("mov.u32 %0, %%cluster_ctarank;" : "=r"(rank));
    const int q = (int)rank;          // 0 or 1
    const int peer = 1 - q;
    const int gate = r >> 6;          // 0..3 (i,f,g,o)
    const int jl = r & 63;
    const int row = gate * HD + q * HALF + jl;
    const int j = q * HALF + r;       // h index owned by update thread r<64

    const uint32_t mbar_addr = smem_u32(&mbar);
    const uint32_t peer_mbar = mapa_u32(mbar_addr, (uint32_t)peer);
    const uint32_t peer_hs   = mapa_u32(smem_u32(&hs[0][0]), (uint32_t)peer);

    if (r == 0) mbar_init(mbar_addr, 1);

    // init h, c
    if (r < HD) hs[0][r] = h0[r];
    float c = (r < HALF) ? c0[j] : 0.f;

    // per-row constants + all 128 weights into registers (64 x u64)
    const float wih  = W_ih[row];
    const float bsum = b_ih[row] + b_hh[row];
    u64 wl[32], wrm[32];  // local-half and remote-half weight pairs
    {
        const u64* wrow = (const u64*)(W_hh + (size_t)row * HD);
        #pragma unroll
        for (int k = 0; k < 32; ++k) wl[k]  = wrow[q * 32 + k];
        #pragma unroll
        for (int k = 0; k < 32; ++k) wrm[k] = wrow[peer * 32 + k];
    }
    __syncthreads();
    cluster_sync();                       // peer mbar init + smem visible

    if (r == 0) mbar_arrive_cluster(peer_mbar);   // prime phase 0 (h0 already local)
    uint32_t parity = 0;

    const int q16 = q * 16, p16 = peer * 16;

    for (int t = 0; t < T; ++t) {
        const int b = t & 1;
        const float xt = __ldg(&x[t]);

        u64 a0 = pack2(fmaf(wih, xt, bsum), 0.f);
        u64 a1 = 0ull, a2 = 0ull, a3 = 0ull;

        const ulonglong2* hv2 = (const ulonglong2*)(&hs[b][0]);  // 32 x 16B

        // local half (already available from our own last-step write)
        #pragma unroll
        for (int k = 0; k < 16; k += 2) {
            ulonglong2 u = hv2[q16 + k];
            ulonglong2 v = hv2[q16 + k + 1];
            a0 = ffma2(wl[2 * k + 0], u.x, a0);
            a1 = ffma2(wl[2 * k + 1], u.y, a1);
            a2 = ffma2(wl[2 * k + 2], v.x, a2);
            a3 = ffma2(wl[2 * k + 3], v.y, a3);
        }

        // wait for peer's h half (latency hidden behind local-half FMAs)
        mbar_wait_cluster(mbar_addr, parity);

        #pragma unroll
        for (int k = 0; k < 16; k += 2) {
            ulonglong2 u = hv2[p16 + k];
            ulonglong2 v = hv2[p16 + k + 1];
            a0 = ffma2(wrm[2 * k + 0], u.x, a0);
            a1 = ffma2(wrm[2 * k + 1], u.y, a1);
            a2 = ffma2(wrm[2 * k + 2], v.x, a2);
            a3 = ffma2(wrm[2 * k + 3], v.y, a3);
        }

        float s0, s1, s2, s3, s4, s5, s6, s7;
        unpack2(a0, s0, s1);
        unpack2(a1, s2, s3);
        unpack2(a2, s4, s5);
        unpack2(a3, s6, s7);
        const float gpre = ((s0 + s1) + (s2 + s3)) + ((s4 + s5) + (s6 + s7));

        gact[r] = (gate == 2) ? tanh_(gpre) : sigm(gpre);
        __syncthreads();

        if (r < HALF) {
            const float iv = gact[r];
            const float fv = gact[HALF + r];
            const float gv = gact[2 * HALF + r];
            const float ov = gact[3 * HALF + r];
            c = fmaf(fv, c, iv * gv);
            const float hnew = ov * tanh_(c);
            hs[1 - b][j] = hnew;                                     // local
            st_remote_f32(peer_hs + (uint32_t)(((1 - b) * HD + j) * 4), hnew);
        }
        __syncthreads();
        if (r == 0) {
            fence_cluster();
            mbar_arrive_cluster(peer_mbar);
        }
        parity ^= 1u;
    }

    // final h_T remote half
    mbar_wait_cluster(mbar_addr, parity);

    if (q == 0) {
        const int bf = T & 1;
        float v = (r < HD) ? hs[bf][r] * W_lin[r] : 0.f;
        #pragma unroll
        for (int o = 16; o > 0; o >>= 1)
            v += __shfl_down_sync(0xFFFFFFFFu, v, o);
        if ((r & 31) == 0) red[r >> 5] = v;
        __syncthreads();
        if (r == 0) out[0] = red[0] + red[1] + red[2] + red[3] + b_lin[0];
    }
}

extern "C" void kernel_launch(void* const* d_in, const int* in_sizes, int n_in,
                              void* d_out, int out_size) {
    const float* x     = (const float*)d_in[0];
    const float* W_ih  = (const float*)d_in[1];
    const float* W_hh  = (const float*)d_in[2];
    const float* b_ih  = (const float*)d_in[3];
    const float* b_hh  = (const float*)d_in[4];
    const float* W_lin = (const float*)d_in[5];
    const float* b_lin = (const float*)d_in[6];
    const float* h0    = (const float*)d_in[7];
    const float* c0    = (const float*)d_in[8];
    float* out = (float*)d_out;

    const int T = in_sizes[0];  // 8192

    lstm_cluster_kernel<<<2, TPC>>>(x, W_ih, W_hh, b_ih, b_hh,
                                    W_lin, b_lin, h0, c0, out, T);
}

// round 3
// speedup vs baseline: 2.3169x; 1.7755x over previous
#include <cuda_runtime.h>
#include <cstdint>

// LSTM T=8192, H=128. Cluster of 2 CTAs x 256 threads. All W_hh in registers.
// Remote h-halves delivered via st.async + transaction mbarriers (no fence,
// no explicit arrive): each of 64 producer threads' stores carries complete_tx
// to the peer's barrier, armed with expect_tx = 64*4 = 256 bytes.

#define HD 128
#define TPC 256
#define HALF 64

typedef unsigned long long u64;

__device__ __forceinline__ u64 ffma2(u64 a, u64 b, u64 c) {
    u64 d;
    asm("fma.rn.f32x2 %0, %1, %2, %3;" : "=l"(d) : "l"(a), "l"(b), "l"(c));
    return d;
}
__device__ __forceinline__ u64 pack2(float lo, float hi) {
    u64 r;
    asm("mov.b64 %0, {%1, %2};" : "=l"(r) : "f"(lo), "f"(hi));
    return r;
}
__device__ __forceinline__ void unpack2(u64 v, float& lo, float& hi) {
    asm("mov.b64 {%0, %1}, %2;" : "=f"(lo), "=f"(hi) : "l"(v));
}
__device__ __forceinline__ float sigm(float x) {
    x = fminf(fmaxf(x, -30.f), 30.f);
    return __fdividef(1.f, 1.f + __expf(-x));
}
__device__ __forceinline__ float tanh_(float x) {
    x = fminf(fmaxf(x, -15.f), 15.f);
    float e = __expf(-2.f * x);
    return __fdividef(1.f - e, 1.f + e);
}
__device__ __forceinline__ uint32_t smem_u32(const void* p) {
    return (uint32_t)__cvta_generic_to_shared(p);
}
__device__ __forceinline__ uint32_t mapa_u32(uint32_t addr, uint32_t rank) {
    uint32_t r;
    asm("mapa.shared::cluster.u32 %0, %1, %2;" : "=r"(r) : "r"(addr), "r"(rank));
    return r;
}
__device__ __forceinline__ void mbar_init(uint32_t a, uint32_t cnt) {
    asm volatile("mbarrier.init.shared.b64 [%0], %1;" :: "r"(a), "r"(cnt) : "memory");
}
__device__ __forceinline__ void mbar_arrive(uint32_t a) {
    asm volatile("mbarrier.arrive.shared.b64 _, [%0];" :: "r"(a) : "memory");
}
__device__ __forceinline__ void mbar_arrive_expect_tx(uint32_t a, uint32_t tx) {
    asm volatile("mbarrier.arrive.expect_tx.shared.b64 _, [%0], %1;"
                 :: "r"(a), "r"(tx) : "memory");
}
// remote store that delivers data + tx-completion to the peer's mbarrier
__device__ __forceinline__ void st_async_f32(uint32_t raddr, float v, uint32_t rmbar) {
    asm volatile(
        "st.async.shared::cluster.mbarrier::complete_tx::bytes.f32 [%0], %1, [%2];"
        :: "r"(raddr), "f"(v), "r"(rmbar) : "memory");
}
__device__ __forceinline__ void mbar_wait(uint32_t a, uint32_t parity) {
    asm volatile(
        "{\n\t"
        ".reg .pred P;\n\t"
        "WL_%=:\n\t"
        "mbarrier.try_wait.parity.acquire.cluster.shared::cta.b64 P, [%0], %1;\n\t"
        "@P bra WD_%=;\n\t"
        "bra WL_%=;\n\t"
        "WD_%=:\n\t"
        "}" :: "r"(a), "r"(parity) : "memory");
}
__device__ __forceinline__ void cluster_sync() {
    asm volatile("barrier.cluster.arrive.aligned;" ::: "memory");
    asm volatile("barrier.cluster.wait.aligned;" ::: "memory");
}

extern "C" __global__ void __launch_bounds__(TPC, 1) __cluster_dims__(2, 1, 1)
lstm_cluster_kernel(const float* __restrict__ x,
                    const float* __restrict__ W_ih,
                    const float* __restrict__ W_hh,
                    const float* __restrict__ b_ih,
                    const float* __restrict__ b_hh,
                    const float* __restrict__ W_lin,
                    const float* __restrict__ b_lin,
                    const float* __restrict__ h0,
                    const float* __restrict__ c0,
                    float* __restrict__ out,
                    int T) {
    __shared__ __align__(16) float hs[2][HD];
    __shared__ float gact[4 * HALF];
    __shared__ float red[8];
    __shared__ __align__(8) u64 mbar[2];

    const int r = threadIdx.x;
    uint32_t rank;
    asm("mov.u32 %0, %%cluster_ctarank;" : "=r"(rank));
    const int q = (int)rank;
    const int peer = 1 - q;
    const int gate = r >> 6;
    const int jl = r & 63;
    const int row = gate * HD + q * HALF + jl;
    const int j = q * HALF + r;     // h index owned by update thread r<64

    const uint32_t mb0 = smem_u32(&mbar[0]);
    const uint32_t mb1 = smem_u32(&mbar[1]);
    const uint32_t peer_mb0 = mapa_u32(mb0, (uint32_t)peer);
    const uint32_t peer_mb1 = mapa_u32(mb1, (uint32_t)peer);
    const uint32_t peer_hs  = mapa_u32(smem_u32(&hs[0][0]), (uint32_t)peer);

    if (r == 0) { mbar_init(mb0, 1); mbar_init(mb1, 1); }

    if (r < HD) hs[0][r] = h0[r];
    float c = (r < HALF) ? c0[j] : 0.f;

    const float wih  = W_ih[row];
    const float bsum = b_ih[row] + b_hh[row];
    u64 wl[32], wrm[32];
    {
        const u64* wrow = (const u64*)(W_hh + (size_t)row * HD);
        #pragma unroll
        for (int k = 0; k < 32; ++k) wl[k]  = wrow[q * 32 + k];
        #pragma unroll
        for (int k = 0; k < 32; ++k) wrm[k] = wrow[peer * 32 + k];
    }
    __syncthreads();
    if (r == 0) {
        mbar_arrive(mb0);                 // step 0 wait passes trivially (h0 local)
        mbar_arrive_expect_tx(mb1, 256);  // arm for step 1's incoming half
    }
    __syncthreads();
    cluster_sync();                       // peer barrier init/arm visible before any st.async

    const int q16 = q * 16, p16 = peer * 16;
    float xt = __ldg(&x[0]);

    for (int t = 0; t < T; ++t) {
        const int b = t & 1;
        const int nb = b ^ 1;
        const uint32_t mbw = b ? mb1 : mb0;
        const uint32_t pmb = nb ? peer_mb1 : peer_mb0;   // peer barrier for step t+1
        const uint32_t parity = (uint32_t)((t >> 1) & 1);

        const float xnext = __ldg(&x[(t + 1 < T) ? (t + 1) : t]);  // prefetch

        u64 a0 = pack2(fmaf(wih, xt, bsum), 0.f);
        u64 a1 = 0ull, a2 = 0ull, a3 = 0ull;

        const ulonglong2* hv2 = (const ulonglong2*)(&hs[b][0]);

        // local half first (no dependence on peer)
        #pragma unroll
        for (int k = 0; k < 16; k += 2) {
            ulonglong2 u = hv2[q16 + k];
            ulonglong2 v = hv2[q16 + k + 1];
            a0 = ffma2(wl[2 * k + 0], u.x, a0);
            a1 = ffma2(wl[2 * k + 1], u.y, a1);
            a2 = ffma2(wl[2 * k + 2], v.x, a2);
            a3 = ffma2(wl[2 * k + 3], v.y, a3);
        }

        mbar_wait(mbw, parity);                       // peer half landed
        if (r == 0) mbar_arrive_expect_tx(mbw, 256);  // re-arm for step t+2

        #pragma unroll
        for (int k = 0; k < 16; k += 2) {
            ulonglong2 u = hv2[p16 + k];
            ulonglong2 v = hv2[p16 + k + 1];
            a0 = ffma2(wrm[2 * k + 0], u.x, a0);
            a1 = ffma2(wrm[2 * k + 1], u.y, a1);
            a2 = ffma2(wrm[2 * k + 2], v.x, a2);
            a3 = ffma2(wrm[2 * k + 3], v.y, a3);
        }

        float s0, s1, s2, s3, s4, s5, s6, s7;
        unpack2(a0, s0, s1);
        unpack2(a1, s2, s3);
        unpack2(a2, s4, s5);
        unpack2(a3, s6, s7);
        const float gpre = ((s0 + s1) + (s2 + s3)) + ((s4 + s5) + (s6 + s7));

        gact[r] = (gate == 2) ? tanh_(gpre) : sigm(gpre);
        __syncthreads();

        if (r < HALF) {
            const float iv = gact[r];
            const float fv = gact[HALF + r];
            const float gv = gact[2 * HALF + r];
            const float ov = gact[3 * HALF + r];
            c = fmaf(fv, c, iv * gv);
            const float hnew = ov * tanh_(c);
            hs[nb][j] = hnew;
            // remote store carries its own completion to the peer's barrier
            st_async_f32(peer_hs + (uint32_t)((nb * HD + j) * 4), hnew, pmb);
        }
        __syncthreads();
        xt = xnext;
    }

    // CTA0 consumes final h: wait for last incoming half, then project.
    if (q == 0) {
        const uint32_t mbw = (T & 1) ? mb1 : mb0;
        mbar_wait(mbw, (uint32_t)((T >> 1) & 1));
        const int bf = T & 1;
        float v = (r < HD) ? hs[bf][r] * W_lin[r] : 0.f;
        #pragma unroll
        for (int o = 16; o > 0; o >>= 1)
            v += __shfl_down_sync(0xFFFFFFFFu, v, o);
        if ((r & 31) == 0) red[r >> 5] = v;
        __syncthreads();
        if (r == 0) out[0] = red[0] + red[1] + red[2] + red[3] + b_lin[0];
    }
    cluster_sync();   // CTA1 must outlive CTA0's final consumption
}

extern "C" void kernel_launch(void* const* d_in, const int* in_sizes, int n_in,
                              void* d_out, int out_size) {
    const float* x     = (const float*)d_in[0];
    const float* W_ih  = (const float*)d_in[1];
    const float* W_hh  = (const float*)d_in[2];
    const float* b_ih  = (const float*)d_in[3];
    const float* b_hh  = (const float*)d_in[4];
    const float* W_lin = (const float*)d_in[5];
    const float* b_lin = (const float*)d_in[6];
    const float* h0    = (const float*)d_in[7];
    const float* c0    = (const float*)d_in[8];
    float* out = (float*)d_out;

    const int T = in_sizes[0];

    lstm_cluster_kernel<<<2, TPC>>>(x, W_ih, W_hh, b_ih, b_hh,
                                    W_lin, b_lin, h0, c0, out, T);
}

// round 4
// speedup vs baseline: 2.3725x; 1.0240x over previous
#include <cuda_runtime.h>
#include <cstdint>

// LSTM T=8192, H=128. Cluster of 2 CTAs x 256 threads. All W_hh in registers.
// Interleaved lane mapping: gate = r&3, element m = r>>2, so lanes 4m..4m+3 of
// one warp hold gates i,f,g,o of element q*64+m. Gate combine via 3 shfl.bfly
// (no smem transpose, one __syncthreads per step). Remote h via st.async +
// transaction mbarriers (expect_tx = 64 floats = 256 B).

#define HD 128
#define TPC 256
#define HALF 64

typedef unsigned long long u64;

__device__ __forceinline__ u64 ffma2(u64 a, u64 b, u64 c) {
    u64 d;
    asm("fma.rn.f32x2 %0, %1, %2, %3;" : "=l"(d) : "l"(a), "l"(b), "l"(c));
    return d;
}
__device__ __forceinline__ u64 pack2(float lo, float hi) {
    u64 r;
    asm("mov.b64 %0, {%1, %2};" : "=l"(r) : "f"(lo), "f"(hi));
    return r;
}
__device__ __forceinline__ void unpack2(u64 v, float& lo, float& hi) {
    asm("mov.b64 {%0, %1}, %2;" : "=f"(lo), "=f"(hi) : "l"(v));
}
__device__ __forceinline__ float sigm(float x) {   // 1/(1+e^-x), clamped
    x = fminf(fmaxf(x, -30.f), 30.f);
    return __fdividef(1.f, 1.f + __expf(-x));
}
__device__ __forceinline__ float tanh_(float x) {
    x = fminf(fmaxf(x, -15.f), 15.f);
    float e = __expf(-2.f * x);
    return __fdividef(1.f - e, 1.f + e);
}
__device__ __forceinline__ uint32_t smem_u32(const void* p) {
    return (uint32_t)__cvta_generic_to_shared(p);
}
__device__ __forceinline__ uint32_t mapa_u32(uint32_t addr, uint32_t rank) {
    uint32_t r;
    asm("mapa.shared::cluster.u32 %0, %1, %2;" : "=r"(r) : "r"(addr), "r"(rank));
    return r;
}
__device__ __forceinline__ void mbar_init(uint32_t a, uint32_t cnt) {
    asm volatile("mbarrier.init.shared.b64 [%0], %1;" :: "r"(a), "r"(cnt) : "memory");
}
__device__ __forceinline__ void mbar_arrive(uint32_t a) {
    asm volatile("mbarrier.arrive.shared.b64 _, [%0];" :: "r"(a) : "memory");
}
__device__ __forceinline__ void mbar_arrive_expect_tx(uint32_t a, uint32_t tx) {
    asm volatile("mbarrier.arrive.expect_tx.shared.b64 _, [%0], %1;"
                 :: "r"(a), "r"(tx) : "memory");
}
__device__ __forceinline__ void st_async_f32(uint32_t raddr, float v, uint32_t rmbar) {
    asm volatile(
        "st.async.shared::cluster.mbarrier::complete_tx::bytes.f32 [%0], %1, [%2];"
        :: "r"(raddr), "f"(v), "r"(rmbar) : "memory");
}
__device__ __forceinline__ void mbar_wait(uint32_t a, uint32_t parity) {
    asm volatile(
        "{\n\t"
        ".reg .pred P;\n\t"
        "WL_%=:\n\t"
        "mbarrier.try_wait.parity.acquire.cluster.shared::cta.b64 P, [%0], %1;\n\t"
        "@P bra WD_%=;\n\t"
        "bra WL_%=;\n\t"
        "WD_%=:\n\t"
        "}" :: "r"(a), "r"(parity) : "memory");
}
__device__ __forceinline__ void cluster_sync() {
    asm volatile("barrier.cluster.arrive.aligned;" ::: "memory");
    asm volatile("barrier.cluster.wait.aligned;" ::: "memory");
}

extern "C" __global__ void __launch_bounds__(TPC, 1) __cluster_dims__(2, 1, 1)
lstm_cluster_kernel(const float* __restrict__ x,
                    const float* __restrict__ W_ih,
                    const float* __restrict__ W_hh,
                    const float* __restrict__ b_ih,
                    const float* __restrict__ b_hh,
                    const float* __restrict__ W_lin,
                    const float* __restrict__ b_lin,
                    const float* __restrict__ h0,
                    const float* __restrict__ c0,
                    float* __restrict__ out,
                    int T) {
    __shared__ __align__(16) float hs[2][HD];
    __shared__ float red[8];
    __shared__ __align__(8) u64 mbar[2];

    const int r = threadIdx.x;
    uint32_t rank;
    asm("mov.u32 %0, %%cluster_ctarank;" : "=r"(rank));
    const int q = (int)rank;
    const int peer = 1 - q;
    const int gate = r & 3;           // i,f,g,o interleaved within warp
    const int m    = r >> 2;          // local element 0..63
    const int row  = gate * HD + q * HALF + m;
    const int j    = q * HALF + m;    // global h index of this group's element
    const bool prod = (gate == 0);    // one producer lane per element

    // activation constants: gate g uses tanh = 2*sigm(2x)-1, others sigm(x)
    const float in_sc  = (gate == 2) ? 2.f : 1.f;
    const float out_sc = (gate == 2) ? 2.f : 1.f;
    const float out_b  = (gate == 2) ? -1.f : 0.f;

    const uint32_t mb0 = smem_u32(&mbar[0]);
    const uint32_t mb1 = smem_u32(&mbar[1]);
    const uint32_t peer_mb0 = mapa_u32(mb0, (uint32_t)peer);
    const uint32_t peer_mb1 = mapa_u32(mb1, (uint32_t)peer);
    const uint32_t peer_hs  = mapa_u32(smem_u32(&hs[0][0]), (uint32_t)peer);

    if (r == 0) { mbar_init(mb0, 1); mbar_init(mb1, 1); }

    if (r < HD) hs[0][r] = h0[r];
    float c = prod ? c0[j] : 0.f;

    const float wih  = W_ih[row];
    const float bsum = b_ih[row] + b_hh[row];
    u64 wl[32], wrm[32];
    {
        const u64* wrow = (const u64*)(W_hh + (size_t)row * HD);
        #pragma unroll
        for (int k = 0; k < 32; ++k) wl[k]  = wrow[q * 32 + k];
        #pragma unroll
        for (int k = 0; k < 32; ++k) wrm[k] = wrow[peer * 32 + k];
    }
    __syncthreads();
    if (r == 0) {
        mbar_arrive(mb0);                 // step 0 passes trivially (h0 already local)
        mbar_arrive_expect_tx(mb1, 256);  // arm for step 1's incoming half
    }
    __syncthreads();
    cluster_sync();                       // peer barrier init/arm visible

    const int q16 = q * 16, p16 = peer * 16;
    float xt = __ldg(&x[0]);

    for (int t = 0; t < T; ++t) {
        const int b  = t & 1;
        const int nb = b ^ 1;
        const uint32_t mbw = b ? mb1 : mb0;
        const uint32_t pmb = nb ? peer_mb1 : peer_mb0;  // barrier for step t+1
        const uint32_t parity = (uint32_t)((t >> 1) & 1);

        const float xnext = __ldg(&x[(t + 1 < T) ? (t + 1) : t]);

        u64 a0 = pack2(fmaf(wih, xt, bsum), 0.f);
        u64 a1 = 0ull, a2 = 0ull, a3 = 0ull;

        const ulonglong2* hv2 = (const ulonglong2*)(&hs[b][0]);

        // local half (independent of peer)
        #pragma unroll
        for (int k = 0; k < 16; k += 2) {
            ulonglong2 u = hv2[q16 + k];
            ulonglong2 v = hv2[q16 + k + 1];
            a0 = ffma2(wl[2 * k + 0], u.x, a0);
            a1 = ffma2(wl[2 * k + 1], u.y, a1);
            a2 = ffma2(wl[2 * k + 2], v.x, a2);
            a3 = ffma2(wl[2 * k + 3], v.y, a3);
        }

        mbar_wait(mbw, parity);                       // peer half landed
        if (r == 0) mbar_arrive_expect_tx(mbw, 256);  // re-arm for step t+2

        #pragma unroll
        for (int k = 0; k < 16; k += 2) {
            ulonglong2 u = hv2[p16 + k];
            ulonglong2 v = hv2[p16 + k + 1];
            a0 = ffma2(wrm[2 * k + 0], u.x, a0);
            a1 = ffma2(wrm[2 * k + 1], u.y, a1);
            a2 = ffma2(wrm[2 * k + 2], v.x, a2);
            a3 = ffma2(wrm[2 * k + 3], v.y, a3);
        }

        float s0, s1, s2, s3, s4, s5, s6, s7;
        unpack2(a0, s0, s1);
        unpack2(a1, s2, s3);
        unpack2(a2, s4, s5);
        unpack2(a3, s6, s7);
        const float gpre = ((s0 + s1) + (s2 + s3)) + ((s4 + s5) + (s6 + s7));

        // unified activation: act = out_sc * sigm(in_sc * x) + out_b
        const float act = fmaf(out_sc, sigm(in_sc * gpre), out_b);

        // gather f,g,o into the i-lane via butterfly shuffles (same warp)
        const float fv = __shfl_xor_sync(0xFFFFFFFFu, act, 1);
        const float gv = __shfl_xor_sync(0xFFFFFFFFu, act, 2);
        const float ov = __shfl_xor_sync(0xFFFFFFFFu, act, 3);

        if (prod) {
            c = fmaf(fv, c, act * gv);           // act == iv on producer lane
            const float hnew = ov * tanh_(c);
            hs[nb][j] = hnew;
            st_async_f32(peer_hs + (uint32_t)((nb * HD + j) * 4), hnew, pmb);
        }
        __syncthreads();
        xt = xnext;
    }

    // CTA0 consumes final h: wait for last incoming half, then project.
    if (q == 0) {
        const uint32_t mbw = (T & 1) ? mb1 : mb0;
        mbar_wait(mbw, (uint32_t)((T >> 1) & 1));
        const int bf = T & 1;
        float v = (r < HD) ? hs[bf][r] * W_lin[r] : 0.f;
        #pragma unroll
        for (int o = 16; o > 0; o >>= 1)
            v += __shfl_down_sync(0xFFFFFFFFu, v, o);
        if ((r & 31) == 0) red[r >> 5] = v;
        __syncthreads();
        if (r == 0) out[0] = red[0] + red[1] + red[2] + red[3] + b_lin[0];
    }
    cluster_sync();   // CTA1 must outlive CTA0's final consumption
}

extern "C" void kernel_launch(void* const* d_in, const int* in_sizes, int n_in,
                              void* d_out, int out_size) {
    const float* x     = (const float*)d_in[0];
    const float* W_ih  = (const float*)d_in[1];
    const float* W_hh  = (const float*)d_in[2];
    const float* b_ih  = (const float*)d_in[3];
    const float* b_hh  = (const float*)d_in[4];
    const float* W_lin = (const float*)d_in[5];
    const float* b_lin = (const float*)d_in[6];
    const float* h0    = (const float*)d_in[7];
    const float* c0    = (const float*)d_in[8];
    float* out = (float*)d_out;

    const int T = in_sizes[0];

    lstm_cluster_kernel<<<2, TPC>>>(x, W_ih, W_hh, b_ih, b_hh,
                                    W_lin, b_lin, h0, c0, out, T);
}